// round 2
// baseline (speedup 1.0000x reference)
#include <cuda_runtime.h>
#include <cuda_bf16.h>
#include <cstdint>

// ---------------------------------------------------------------------------
// BitNet-style MLP:
//   h = bitlinear(x, norm1_w, w1)  -> StarReLU -> y = bitlinear(h, norm2_w, w2)
// Exact-integer formulation: activation quant codes q in [-128,127] and ternary
// weight codes t in {-1,0,1} are exactly representable in bf16; bf16 MMA with
// fp32 accumulate computes the integer GEMM exactly (|acc| <= 1024*127 < 2^24).
// Scales applied in the GEMM epilogue.
//
// NOTE: all scratch lives in __device__ globals and is referenced ONLY from
// device code (host code must never take the address of a __device__ symbol).
// ---------------------------------------------------------------------------

constexpr int MTOK = 8192;   // 4 * 2048 tokens
constexpr int DIM  = 1024;
constexpr int HID  = 4096;
constexpr int WNEL = HID * DIM;  // 4194304 elements in each weight

// ------------------------- device scratch ----------------------------------
__device__ __align__(16) __nv_bfloat16 g_xq[MTOK * DIM];            // 16 MB
__device__ __align__(16) __nv_bfloat16 g_hq[(size_t)MTOK * HID];    // 64 MB
__device__ __align__(16) __nv_bfloat16 g_w1q[WNEL];                 //  8 MB
__device__ __align__(16) __nv_bfloat16 g_w2q[WNEL];                 //  8 MB
__device__ __align__(16) float         g_h[(size_t)MTOK * HID];     // 128 MB
__device__ float g_xs[MTOK];      // per-token dequant factor (1/scale) for x
__device__ float g_hs[MTOK];      // per-token dequant factor for h
__device__ float g_part[2][1024]; // partial |w| sums
__device__ float g_scales[4];     // s1, 1/s1, s2, 1/s2

// ------------------------- reductions --------------------------------------
__device__ __forceinline__ float warpSum(float v) {
#pragma unroll
    for (int o = 16; o > 0; o >>= 1) v += __shfl_xor_sync(0xffffffffu, v, o);
    return v;
}
__device__ __forceinline__ float warpMax(float v) {
#pragma unroll
    for (int o = 16; o > 0; o >>= 1) v = fmaxf(v, __shfl_xor_sync(0xffffffffu, v, o));
    return v;
}
// blockDim.x == 256. Deterministic (fixed order).
__device__ float blockSum(float v) {
    __shared__ float sh[8];
    v = warpSum(v);
    if ((threadIdx.x & 31) == 0) sh[threadIdx.x >> 5] = v;
    __syncthreads();
    if (threadIdx.x == 0) {
        float t = sh[0];
#pragma unroll
        for (int i = 1; i < 8; i++) t += sh[i];
        sh[0] = t;
    }
    __syncthreads();
    float r = sh[0];
    __syncthreads();
    return r;
}
__device__ float blockMax(float v) {
    __shared__ float sh[8];
    v = warpMax(v);
    if ((threadIdx.x & 31) == 0) sh[threadIdx.x >> 5] = v;
    __syncthreads();
    if (threadIdx.x == 0) {
        float t = sh[0];
#pragma unroll
        for (int i = 1; i < 8; i++) t = fmaxf(t, sh[i]);
        sh[0] = t;
    }
    __syncthreads();
    float r = sh[0];
    __syncthreads();
    return r;
}

// ------------------------- weight quantization ------------------------------
__global__ void absmean_part(const float* __restrict__ w, int which) {
    float s = 0.f;
    for (int i = blockIdx.x * 256 + threadIdx.x; i < WNEL; i += 1024 * 256)
        s += fabsf(w[i]);
    s = blockSum(s);
    if (threadIdx.x == 0) g_part[which][blockIdx.x] = s;
}

__global__ void finalize_scales() {
    float s1 = 0.f, s2 = 0.f;
    for (int i = threadIdx.x; i < 1024; i += 256) {
        s1 += g_part[0][i];
        s2 += g_part[1][i];
    }
    s1 = blockSum(s1);
    s2 = blockSum(s2);
    if (threadIdx.x == 0) {
        float sc1 = 1.f / fmaxf(s1 / (float)WNEL, 1e-5f);
        float sc2 = 1.f / fmaxf(s2 / (float)WNEL, 1e-5f);
        g_scales[0] = sc1; g_scales[1] = 1.f / sc1;
        g_scales[2] = sc2; g_scales[3] = 1.f / sc2;
    }
}

// ternarize weights -> bf16 codes. grid = WNEL/1024, block = 256, 4 elems/thread
__global__ void weight_quant_k(const float* __restrict__ w, int which) {
    __nv_bfloat16* __restrict__ wq = which ? g_w2q : g_w1q;
    float s = g_scales[which * 2];
    size_t i = ((size_t)blockIdx.x * 256 + threadIdx.x) * 4;
    float4 v = *(const float4*)(w + i);
    float t0 = fminf(fmaxf(rintf(v.x * s), -1.f), 1.f);
    float t1 = fminf(fmaxf(rintf(v.y * s), -1.f), 1.f);
    float t2 = fminf(fmaxf(rintf(v.z * s), -1.f), 1.f);
    float t3 = fminf(fmaxf(rintf(v.w * s), -1.f), 1.f);
    __nv_bfloat162 p0 = __nv_bfloat162(__float2bfloat16_rn(t0), __float2bfloat16_rn(t1));
    __nv_bfloat162 p1 = __nv_bfloat162(__float2bfloat16_rn(t2), __float2bfloat16_rn(t3));
    uint2 pk;
    pk.x = *(const unsigned int*)&p0;
    pk.y = *(const unsigned int*)&p1;
    *(uint2*)(wq + i) = pk;
}

// ------------------------- rmsnorm + activation quant -----------------------
// One block (256 threads) per token.
// STAGE 0: in = x (host ptr, D=1024)      -> writes g_xq / g_xs
// STAGE 1: in = g_h (device, D=4096)     -> writes g_hq / g_hs
template <int D, int STAGE>
__global__ void act_quant(const float* __restrict__ xin, const float* __restrict__ nw) {
    constexpr int E = D / 1024;  // float4's per thread
    const float* __restrict__ in = (STAGE == 0) ? xin : g_h;
    __nv_bfloat16* __restrict__ xq = (STAGE == 0) ? g_xq : g_hq;
    float* __restrict__ xs = (STAGE == 0) ? g_xs : g_hs;
    size_t base = (size_t)blockIdx.x * D;

    float4 v[E], wv[E];
    float ss = 0.f;
#pragma unroll
    for (int e = 0; e < E; e++) {
        int idx = (e * 256 + threadIdx.x) * 4;
        v[e]  = *(const float4*)(in + base + idx);
        wv[e] = *(const float4*)(nw + idx);
        ss += v[e].x * v[e].x + v[e].y * v[e].y + v[e].z * v[e].z + v[e].w * v[e].w;
    }
    ss = blockSum(ss);
    float rsq = rsqrtf(ss / (float)D + 1e-8f);

    float mx = 0.f;
#pragma unroll
    for (int e = 0; e < E; e++) {
        v[e].x = v[e].x * rsq * wv[e].x;
        v[e].y = v[e].y * rsq * wv[e].y;
        v[e].z = v[e].z * rsq * wv[e].z;
        v[e].w = v[e].w * rsq * wv[e].w;
        mx = fmaxf(mx, fmaxf(fmaxf(fabsf(v[e].x), fabsf(v[e].y)),
                             fmaxf(fabsf(v[e].z), fabsf(v[e].w))));
    }
    mx = blockMax(mx);
    float sc = 127.f / fmaxf(mx, 1e-5f);

#pragma unroll
    for (int e = 0; e < E; e++) {
        int idx = (e * 256 + threadIdx.x) * 4;
        float q0 = fminf(fmaxf(rintf(v[e].x * sc), -128.f), 127.f);
        float q1 = fminf(fmaxf(rintf(v[e].y * sc), -128.f), 127.f);
        float q2 = fminf(fmaxf(rintf(v[e].z * sc), -128.f), 127.f);
        float q3 = fminf(fmaxf(rintf(v[e].w * sc), -128.f), 127.f);
        __nv_bfloat162 p0 = __nv_bfloat162(__float2bfloat16_rn(q0), __float2bfloat16_rn(q1));
        __nv_bfloat162 p1 = __nv_bfloat162(__float2bfloat16_rn(q2), __float2bfloat16_rn(q3));
        uint2 pk;
        pk.x = *(const unsigned int*)&p0;
        pk.y = *(const unsigned int*)&p1;
        *(uint2*)(xq + base + idx) = pk;
    }
    if (threadIdx.x == 0) xs[blockIdx.x] = 1.f / sc;
}

// ------------------------- GEMM --------------------------------------------
__device__ __forceinline__ void mma16816(float* d, const uint32_t* a, const uint32_t* b) {
    asm volatile(
        "mma.sync.aligned.m16n8k16.row.col.f32.bf16.bf16.f32 "
        "{%0,%1,%2,%3},{%4,%5,%6,%7},{%8,%9},{%0,%1,%2,%3};"
        : "+f"(d[0]), "+f"(d[1]), "+f"(d[2]), "+f"(d[3])
        : "r"(a[0]), "r"(a[1]), "r"(a[2]), "r"(a[3]), "r"(b[0]), "r"(b[1]));
}

#define CP_ASYNC16(dst, src) \
    asm volatile("cp.async.cg.shared.global [%0], [%1], 16;\n" ::"r"(dst), "l"(src))

// C[m,n] = sum_k A[m,k]*B[n,k], A:[M,K] bf16 codes, B:[N,K] bf16 codes.
// MODE 1: A=g_xq, B=g_w1q -> StarReLU epilogue -> g_h (fp32)
// MODE 2: A=g_hq, B=g_w2q -> scaled epilogue  -> Cout (d_out, fp32)
template <int K, int MODE>
__global__ void __launch_bounds__(256) gemm_q(float* __restrict__ Cout,
                                              const float* __restrict__ act_s,
                                              const float* __restrict__ act_b) {
    constexpr int BM = 128, BN = 128, BK = 32, PK = 40;  // PK: padded pitch (80B)
    constexpr int KT = K / BK;
    const __nv_bfloat16* __restrict__ A = (MODE == 1) ? g_xq : g_hq;
    const __nv_bfloat16* __restrict__ B = (MODE == 1) ? g_w1q : g_w2q;
    const float* __restrict__ rsc = (MODE == 1) ? g_xs : g_hs;
    const int N = (MODE == 1) ? HID : DIM;
    float* __restrict__ C = (MODE == 1) ? g_h : Cout;

    __shared__ __nv_bfloat16 sA[2][BM * PK];
    __shared__ __nv_bfloat16 sB[2][BN * PK];

    const int tid = threadIdx.x;
    // loader mapping: 256 threads, each two 16B chunks per tile per matrix
    const int lr = tid >> 2;   // 0..63
    const int lc = tid & 3;    // 0..3 (16B chunks across BK=32 bf16)
    const __nv_bfloat16* gA = A + ((size_t)blockIdx.y * BM + lr) * K + lc * 8;
    const __nv_bfloat16* gB = B + ((size_t)blockIdx.x * BN + lr) * K + lc * 8;
    const uint32_t sAb = (uint32_t)__cvta_generic_to_shared(&sA[0][0]);
    const uint32_t sBb = (uint32_t)__cvta_generic_to_shared(&sB[0][0]);
    const uint32_t dA0 = sAb + (lr * PK + lc * 8) * 2;
    const uint32_t dA1 = sAb + ((lr + 64) * PK + lc * 8) * 2;
    const uint32_t dB0 = sBb + (lr * PK + lc * 8) * 2;
    const uint32_t dB1 = sBb + ((lr + 64) * PK + lc * 8) * 2;

    auto load_stage = [&](int st, int kt) {
        const size_t off = (size_t)kt * BK;
        const uint32_t so = st * BM * PK * 2;
        CP_ASYNC16(dA0 + so, gA + off);
        CP_ASYNC16(dA1 + so, gA + off + (size_t)64 * K);
        CP_ASYNC16(dB0 + so, gB + off);
        CP_ASYNC16(dB1 + so, gB + off + (size_t)64 * K);
        asm volatile("cp.async.commit_group;\n" ::);
    };

    const int lane = tid & 31, w = tid >> 5;
    const int wm = (w & 1) * 64;       // 2 warps over M
    const int wn = (w >> 1) * 32;      // 4 warps over N
    const int g = lane >> 2, tg = lane & 3;

    float acc[4][4][4];
#pragma unroll
    for (int mt = 0; mt < 4; mt++)
#pragma unroll
        for (int nt = 0; nt < 4; nt++)
#pragma unroll
            for (int r = 0; r < 4; r++) acc[mt][nt][r] = 0.f;

    load_stage(0, 0);

    for (int kt = 0; kt < KT; ++kt) {
        if (kt + 1 < KT) {
            load_stage((kt + 1) & 1, kt + 1);
            asm volatile("cp.async.wait_group 1;\n" ::: "memory");
        } else {
            asm volatile("cp.async.wait_group 0;\n" ::: "memory");
        }
        __syncthreads();

        const __nv_bfloat16* a_s = sA[kt & 1];
        const __nv_bfloat16* b_s = sB[kt & 1];
#pragma unroll
        for (int ks = 0; ks < 2; ks++) {
            uint32_t af[4][4], bfr[4][2];
#pragma unroll
            for (int mt = 0; mt < 4; mt++) {
                const __nv_bfloat16* p = a_s + (wm + mt * 16 + g) * PK + ks * 16 + tg * 2;
                af[mt][0] = *(const uint32_t*)p;
                af[mt][2] = *(const uint32_t*)(p + 8);
                const __nv_bfloat16* p8 = p + 8 * PK;
                af[mt][1] = *(const uint32_t*)p8;
                af[mt][3] = *(const uint32_t*)(p8 + 8);
            }
#pragma unroll
            for (int nt = 0; nt < 4; nt++) {
                const __nv_bfloat16* p = b_s + (wn + nt * 8 + g) * PK + ks * 16 + tg * 2;
                bfr[nt][0] = *(const uint32_t*)p;
                bfr[nt][1] = *(const uint32_t*)(p + 8);
            }
#pragma unroll
            for (int mt = 0; mt < 4; mt++)
#pragma unroll
                for (int nt = 0; nt < 4; nt++) mma16816(acc[mt][nt], af[mt], bfr[nt]);
        }
        __syncthreads();
    }

    // epilogue
    const float rw = g_scales[(MODE == 1) ? 1 : 3];
    float vs = 0.f, vb = 0.f;
    if (MODE == 1) { vs = *act_s; vb = *act_b; }

#pragma unroll
    for (int mt = 0; mt < 4; mt++) {
        const int m = blockIdx.y * BM + wm + mt * 16 + g;
        const float f0 = rsc[m] * rw;
        const float f1 = rsc[m + 8] * rw;
#pragma unroll
        for (int nt = 0; nt < 4; nt++) {
            const int n = blockIdx.x * BN + wn + nt * 8 + tg * 2;
            float v0 = acc[mt][nt][0] * f0;
            float v1 = acc[mt][nt][1] * f0;
            float v2 = acc[mt][nt][2] * f1;
            float v3 = acc[mt][nt][3] * f1;
            if (MODE == 1) {
                float r0 = fmaxf(v0, 0.f), r1 = fmaxf(v1, 0.f);
                float r2 = fmaxf(v2, 0.f), r3 = fmaxf(v3, 0.f);
                v0 = vs * r0 * r0 + vb;
                v1 = vs * r1 * r1 + vb;
                v2 = vs * r2 * r2 + vb;
                v3 = vs * r3 * r3 + vb;
            }
            *(float2*)&C[(size_t)m * N + n]       = make_float2(v0, v1);
            *(float2*)&C[(size_t)(m + 8) * N + n] = make_float2(v2, v3);
        }
    }
}

// ------------------------- launch ------------------------------------------
extern "C" void kernel_launch(void* const* d_in, const int* in_sizes, int n_in,
                              void* d_out, int out_size) {
    const float* x    = (const float*)d_in[0];   // [4,2048,1024]
    const float* nw1  = (const float*)d_in[1];   // [1024]
    const float* w1   = (const float*)d_in[2];   // [4096,1024]
    const float* as_p = (const float*)d_in[3];   // [1]
    const float* ab_p = (const float*)d_in[4];   // [1]
    const float* nw2  = (const float*)d_in[5];   // [4096]
    const float* w2   = (const float*)d_in[6];   // [1024,4096]
    float* out = (float*)d_out;

    // weight scales (deterministic two-stage reductions)
    absmean_part<<<1024, 256>>>(w1, 0);
    absmean_part<<<1024, 256>>>(w2, 1);
    finalize_scales<<<1, 256>>>();

    // ternarize weights
    weight_quant_k<<<WNEL / 1024, 256>>>(w1, 0);
    weight_quant_k<<<WNEL / 1024, 256>>>(w2, 1);

    // rmsnorm1 + activation quant (x -> g_xq/g_xs)
    act_quant<DIM, 0><<<MTOK, 256>>>(x, nw1);

    // GEMM1 + dequant + StarReLU -> g_h
    gemm_q<DIM, 1><<<dim3(HID / 128, MTOK / 128), 256>>>(nullptr, as_p, ab_p);

    // rmsnorm2 + activation quant (g_h -> g_hq/g_hs)
    act_quant<HID, 1><<<MTOK, 256>>>(nullptr, nw2);

    // GEMM2 + dequant -> out
    gemm_q<HID, 2><<<dim3(DIM / 128, MTOK / 128), 256>>>(out, nullptr, nullptr);
}